// round 12
// baseline (speedup 1.0000x reference)
#include <cuda_runtime.h>
#include <cstdint>

#define T_STEPS 2048
#define BATCH   32
#define HID     512
#define GATES   2048   // 4*H
#define DIN     512
#define NBLK    128
#define RTH     512
#define REC_SMEM_BYTES (128 * 1024)

// Scratch (device globals — no allocation allowed in kernel_launch).
__device__ __align__(16) float g_xp [(size_t)BATCH * T_STEPS * GATES]; // [b*T+t][col]
__device__ __align__(16) float g_xp2[(size_t)BATCH * GATES * T_STEPS]; // [b][col][t]
__device__ __align__(16) float g_h2 [2 * HID * BATCH];                 // [buf][k][b]
__device__ __align__(16) unsigned g_grp[16 * 8];                       // 16 group ctrs, 32B stride
__device__ unsigned g_ctr;                                             // central ctr (monotone)
__device__ unsigned g_release;                                         // release word (monotone)

// ---------------------------------------------------------------------------
// Kernel 1: x_proj GEMM  (unchanged — known good)
// ---------------------------------------------------------------------------
__global__ void __launch_bounds__(256) xproj_gemm(const float* __restrict__ X,
                                                  const float* __restrict__ Wi)
{
    __shared__ float As[16][128];
    __shared__ float Bs[16][128];
    const int tid = threadIdx.x;
    const int row0 = blockIdx.y * 128;
    const int col0 = blockIdx.x * 128;
    const int tx = tid & 15, ty = tid >> 4;

    unsigned long long acc2[8][4];
    #pragma unroll
    for (int i = 0; i < 8; i++)
        #pragma unroll
        for (int j = 0; j < 4; j++) acc2[i][j] = 0ull;

    for (int k0 = 0; k0 < DIN; k0 += 16) {
        #pragma unroll
        for (int i = 0; i < 2; i++) {
            int j = tid + i * 256;
            int r = j >> 2, kq = (j & 3) << 2;
            float4 v = *(const float4*)(X + (size_t)(row0 + r) * DIN + k0 + kq);
            As[kq + 0][r] = v.x; As[kq + 1][r] = v.y;
            As[kq + 2][r] = v.z; As[kq + 3][r] = v.w;
        }
        #pragma unroll
        for (int i = 0; i < 2; i++) {
            int j = tid + i * 256;
            int kk = j >> 5, c4 = (j & 31) << 2;
            *(float4*)(&Bs[kk][c4]) =
                *(const float4*)(Wi + (size_t)(k0 + kk) * GATES + col0 + c4);
        }
        __syncthreads();
        #pragma unroll
        for (int kk = 0; kk < 16; kk++) {
            float a[8];
            *(float4*)&a[0] = *(const float4*)&As[kk][ty * 8];
            *(float4*)&a[4] = *(const float4*)&As[kk][ty * 8 + 4];
            ulonglong2 b01 = *(const ulonglong2*)&Bs[kk][tx * 8];
            ulonglong2 b23 = *(const ulonglong2*)&Bs[kk][tx * 8 + 4];
            #pragma unroll
            for (int i = 0; i < 8; i++) {
                unsigned long long aa;
                asm("mov.b64 %0, {%1, %1};" : "=l"(aa) : "f"(a[i]));
                asm("fma.rn.f32x2 %0, %1, %2, %0;" : "+l"(acc2[i][0]) : "l"(aa), "l"(b01.x));
                asm("fma.rn.f32x2 %0, %1, %2, %0;" : "+l"(acc2[i][1]) : "l"(aa), "l"(b01.y));
                asm("fma.rn.f32x2 %0, %1, %2, %0;" : "+l"(acc2[i][2]) : "l"(aa), "l"(b23.x));
                asm("fma.rn.f32x2 %0, %1, %2, %0;" : "+l"(acc2[i][3]) : "l"(aa), "l"(b23.y));
            }
        }
        __syncthreads();
    }
    #pragma unroll
    for (int i = 0; i < 8; i++) {
        size_t r = (size_t)row0 + ty * 8 + i;
        float o[8];
        #pragma unroll
        for (int j = 0; j < 4; j++)
            asm("mov.b64 {%0, %1}, %2;" : "=f"(o[2*j]), "=f"(o[2*j+1]) : "l"(acc2[i][j]));
        *(float4*)(g_xp + r * GATES + col0 + tx * 8)     = *(float4*)&o[0];
        *(float4*)(g_xp + r * GATES + col0 + tx * 8 + 4) = *(float4*)&o[4];
    }
}

// ---------------------------------------------------------------------------
// Kernel 1b: transpose x_proj [b*T+t][col] -> [b][col][t]
// ---------------------------------------------------------------------------
__global__ void __launch_bounds__(256) xp_transpose()
{
    __shared__ float tile[32][33];
    const int tx = threadIdx.x & 31, ty = threadIdx.x >> 5;  // ty 0..7
    const size_t r0 = (size_t)blockIdx.y * 32;               // row = b*T + t
    const int c0 = blockIdx.x * 32;
    #pragma unroll
    for (int i = 0; i < 4; i++)
        tile[ty + i * 8][tx] = g_xp[(r0 + ty + i * 8) * GATES + c0 + tx];
    __syncthreads();
    const int bb = (int)(r0 >> 11);
    const int t0 = (int)(r0 & 2047);
    #pragma unroll
    for (int i = 0; i < 4; i++)
        g_xp2[((size_t)bb * GATES + c0 + ty + i * 8) * T_STEPS + t0 + tx] =
            tile[tx][ty + i * 8];
}

// ---------------------------------------------------------------------------
// Init: counters + h0 -> g_h2 buffer 0 in [k][b] layout
// ---------------------------------------------------------------------------
__global__ void init_kernel(const float* __restrict__ h0)
{
    int i = blockIdx.x * blockDim.x + threadIdx.x;
    if (i < 16 * 8) g_grp[i] = 0u;
    if (i == 0) { g_ctr = 0u; g_release = 0u; }
    if (i < HID * BATCH) {
        int k = i >> 5, b = i & 31;
        g_h2[i] = h0[b * HID + k];
    }
}

// ---------------------------------------------------------------------------
// Kernel 2: persistent LSTM recurrence — EXACT R6 structure; the only change
// is inside the tid==0 barrier region: 128-deep single-counter atomic chain
// replaced by a 16x8 monotonic counter tree feeding the same release word.
// ---------------------------------------------------------------------------
__device__ __forceinline__ float fast_sigmoid(float x) {
    return __fdividef(1.0f, 1.0f + __expf(-x));
}
__device__ __forceinline__ float fast_tanh(float x) {
    return __fdividef(2.0f, 1.0f + __expf(-2.0f * x)) - 1.0f;
}

__global__ void __launch_bounds__(RTH) lstm_recurrent(
    const float* __restrict__ c0,
    const float* __restrict__ Wh,
    const float* __restrict__ bias,
    float* __restrict__ out)
{
    extern __shared__ float sm[];
    float* hsw = sm;                   // 16 warps x [32 k][32 b]       = 16384 f
    float* wsm = sm + 16384;           // [128 jg][16 c][4 ksub]        =  8192 f
    float* red = sm + 16384 + 8192;    // [16 c][16 w][32 b]            =  8192 f

    const int tid = threadIdx.x;
    const int w   = tid >> 5;
    const int b   = tid & 31;
    const int bi  = blockIdx.x;
    const int grp = bi & 15;

    // One-time: fill wsm. wsm[jg][c][ks] = Wh[(4jg+ks)][colglobal(c)]
    #pragma unroll
    for (int i = 0; i < 16; i++) {
        int idx = tid + i * RTH;
        int jg = idx >> 6, rem = idx & 63, c = rem >> 2, ks = rem & 3;
        int col = (c >> 2) * HID + bi * 4 + (c & 3);
        wsm[idx] = Wh[(size_t)(jg * 4 + ks) * GATES + col];
    }

    // Gate-thread state (warps 0-3): m = w, hcol = 4bi + m
    const int hcol = bi * 4 + w;
    float bq[4];
    const float* xq[4];
    float c_st = 0.0f;
    if (w < 4) {
        #pragma unroll
        for (int q = 0; q < 4; q++) {
            bq[q] = bias[q * HID + hcol];
            xq[q] = g_xp2 + ((size_t)b * GATES + q * HID + hcol) * T_STEPS;
        }
        c_st = c0[b * HID + hcol];
    }
    __syncthreads();

    float* hsw_w = hsw + w * 1024;
    const ulonglong2* wsm_w = (const ulonglong2*)wsm + w * 8 * 16;

    float4 xv[4];
    #pragma unroll 2
    for (int t = 0; t < T_STEPS; t++) {
        // Stage own 4KB h slice: coalesced LDG.128 (L2, bypass L1) -> STS.128
        {
            const float4* src = (const float4*)(g_h2 + (t & 1) * (HID * BATCH)) + w * 256;
            float4 hv[8];
            #pragma unroll
            for (int i = 0; i < 8; i++) hv[i] = __ldcg(src + b + i * 32);
            float4* dst = (float4*)hsw_w;
            #pragma unroll
            for (int i = 0; i < 8; i++) dst[b + i * 32] = hv[i];
            __syncwarp();
        }

        // Prefetch x_proj for 4 steps (gate threads only)
        if (w < 4 && (t & 3) == 0) {
            #pragma unroll
            for (int q = 0; q < 4; q++) xv[q] = *(const float4*)(xq[q] + t);
        }

        // Partial z for 16 cols over this warp's 32-k chunk
        unsigned long long acc[16];
        #pragma unroll
        for (int c = 0; c < 16; c++) acc[c] = 0ull;
        #pragma unroll
        for (int kq = 0; kq < 8; kq++) {
            float h0v = hsw_w[(kq * 4 + 0) * 32 + b];
            float h1v = hsw_w[(kq * 4 + 1) * 32 + b];
            float h2v = hsw_w[(kq * 4 + 2) * 32 + b];
            float h3v = hsw_w[(kq * 4 + 3) * 32 + b];
            unsigned long long X01, X23;
            asm("mov.b64 %0, {%1, %2};" : "=l"(X01) : "f"(h0v), "f"(h1v));
            asm("mov.b64 %0, {%1, %2};" : "=l"(X23) : "f"(h2v), "f"(h3v));
            const ulonglong2* wq = wsm_w + kq * 16;
            #pragma unroll
            for (int c = 0; c < 16; c++) {
                ulonglong2 wv = wq[c];   // broadcast LDS.128
                asm("fma.rn.f32x2 %0, %1, %2, %0;" : "+l"(acc[c]) : "l"(X01), "l"(wv.x));
                asm("fma.rn.f32x2 %0, %1, %2, %0;" : "+l"(acc[c]) : "l"(X23), "l"(wv.y));
            }
        }
        #pragma unroll
        for (int c = 0; c < 16; c++) {
            float lo, hi;
            asm("mov.b64 {%0, %1}, %2;" : "=f"(lo), "=f"(hi) : "l"(acc[c]));
            red[(c * 16 + w) * 32 + b] = lo + hi;
        }
        __syncthreads();   // red complete

        if (w < 4) {
            float z[4];
            #pragma unroll
            for (int q = 0; q < 4; q++) {
                const float* rp = red + ((q * 4 + w) * 16) * 32 + b;
                float s0 = 0.f, s1 = 0.f, s2 = 0.f, s3 = 0.f;
                #pragma unroll
                for (int wk = 0; wk < 16; wk += 4) {
                    s0 += rp[(wk + 0) * 32];
                    s1 += rp[(wk + 1) * 32];
                    s2 += rp[(wk + 2) * 32];
                    s3 += rp[(wk + 3) * 32];
                }
                float xc = (t & 3) == 0 ? xv[q].x :
                           (t & 3) == 1 ? xv[q].y :
                           (t & 3) == 2 ? xv[q].z : xv[q].w;
                z[q] = ((s0 + s1) + (s2 + s3)) + xc + bq[q];
            }
            float ig = fast_sigmoid(z[0]);
            float fg = fast_sigmoid(z[1]);
            float gg = fast_tanh(z[2]);
            float og = fast_sigmoid(z[3]);
            c_st = fg * c_st + ig * gg;
            float hn = og * fast_tanh(c_st);
            g_h2[((t + 1) & 1) * (HID * BATCH) + hcol * 32 + b] = hn;
            out[(size_t)b * T_STEPS * HID + (size_t)t * HID + hcol] = hn;
            __threadfence();
        }
        __syncthreads();

        // Grid barrier (R6 spin; two-level monotonic arrival tree, no resets).
        // Group grp gets 8 arrivals/step -> counter hits 8(t+1); the block
        // completing its group forwards to g_ctr; the block completing g_ctr
        // (16 forwards/step -> 16(t+1)) writes the release word.
        if (tid == 0) {
            __threadfence();
            bool released = false;
            unsigned a = atomicAdd(&g_grp[grp * 8], 1u);
            if (a + 1u == 8u * (unsigned)(t + 1)) {
                unsigned cc = atomicAdd(&g_ctr, 1u);
                if (cc + 1u == 16u * (unsigned)(t + 1)) {
                    asm volatile("st.release.gpu.global.b32 [%0], %1;"
                                 :: "l"(&g_release), "r"((unsigned)(t + 1)) : "memory");
                    released = true;
                }
            }
            if (!released) {
                unsigned r;
                do {
                    asm volatile("ld.acquire.gpu.global.b32 %0, [%1];"
                                 : "=r"(r) : "l"(&g_release) : "memory");
                } while (r < (unsigned)(t + 1));
            }
            __threadfence();
        }
        __syncthreads();
    }
}

// ---------------------------------------------------------------------------
extern "C" void kernel_launch(void* const* d_in, const int* in_sizes, int n_in,
                              void* d_out, int out_size)
{
    const float* inputs = (const float*)d_in[0];   // [B,T,D]
    // d_in[1] = input_paddings (all valid, unused)
    const float* c0   = (const float*)d_in[2];     // [B,H]
    const float* h0   = (const float*)d_in[3];     // [B,H]
    const float* Wi   = (const float*)d_in[4];     // [D,4H]
    const float* Wh   = (const float*)d_in[5];     // [H,4H]
    const float* bias = (const float*)d_in[6];     // [4H]
    float* out = (float*)d_out;                    // [B,T,H]

    cudaFuncSetAttribute(lstm_recurrent,
                         cudaFuncAttributeMaxDynamicSharedMemorySize,
                         REC_SMEM_BYTES);

    xproj_gemm<<<dim3(GATES / 128, (BATCH * T_STEPS) / 128), 256>>>(inputs, Wi);
    xp_transpose<<<dim3(GATES / 32, (BATCH * T_STEPS) / 32), 256>>>();
    init_kernel<<<(HID * BATCH + 255) / 256, 256>>>(h0);
    lstm_recurrent<<<NBLK, RTH, REC_SMEM_BYTES>>>(c0, Wh, bias, out);
}